// round 15
// baseline (speedup 1.0000x reference)
#include <cuda_runtime.h>
#include <cuda_bf16.h>
#include <mma.h>
#include <cstdint>

using namespace nvcuda;

#define Lc   8
#define Hc   4
#define Qc   64
#define Dc   512
#define Nc   2048
#define DFFc 2048
#define KVROWS (Hc * Dc + Hc * Qc)   // 2304 output cols: Y then KX
#define YROWS  (Hc * Dc)             // 2048

// ---------------- device scratch (no allocations allowed) ----------------
__device__ float g_X[Nc * Dc];
__device__ float g_attn[Nc * Dc];
__device__ float g_Y[Nc * YROWS];
__device__ __nv_bfloat16 g_KVh[Lc * KVROWS * Dc], g_KVl[Lc * KVROWS * Dc];
__device__ __nv_bfloat16 g_W1h[Lc * DFFc * Dc],   g_W1l[Lc * DFFc * Dc];
__device__ __nv_bfloat16 g_W2h[Lc * Dc * DFFc],   g_W2l[Lc * Dc * DFFc];
__device__ __nv_bfloat16 g_Xh[Nc * Dc],           g_Xl[Nc * Dc];
__device__ __nv_bfloat16 g_Ath[Nc * Dc],          g_Atl[Nc * Dc];
__device__ __nv_bfloat16 g_F1h[Nc * DFFc],        g_F1l[Nc * DFFc];
__device__ __nv_bfloat16 g_KXh[Nc * 256],         g_KXl[Nc * 256];

// ---------------- helpers --------------------------------------------------
__device__ __forceinline__ uint32_t smem_u32(const void* p) {
    uint32_t a;
    asm("{ .reg .u64 t; cvta.to.shared.u64 t, %1; cvt.u32.u64 %0, t; }"
        : "=r"(a) : "l"(p));
    return a;
}
__device__ __forceinline__ void cp16(void* s, const void* g) {
    asm volatile("cp.async.cg.shared.global [%0], [%1], 16;"
                 :: "r"(smem_u32(s)), "l"(g) : "memory");
}
__device__ __forceinline__ void cp_commit() {
    asm volatile("cp.async.commit_group;" ::: "memory");
}
template<int N> __device__ __forceinline__ void cp_wait() {
    asm volatile("cp.async.wait_group %0;" :: "n"(N) : "memory");
}

__device__ __forceinline__ void split_store4(__nv_bfloat16* __restrict__ Hd,
                                             __nv_bfloat16* __restrict__ Ld,
                                             float4 v)
{
    __nv_bfloat162 h0 = __floats2bfloat162_rn(v.x, v.y);
    __nv_bfloat162 h1 = __floats2bfloat162_rn(v.z, v.w);
    float2 f0 = __bfloat1622float2(h0);
    float2 f1 = __bfloat1622float2(h1);
    __nv_bfloat162 l0 = __floats2bfloat162_rn(v.x - f0.x, v.y - f0.y);
    __nv_bfloat162 l1 = __floats2bfloat162_rn(v.z - f1.x, v.w - f1.y);
    *(__nv_bfloat162*)(Hd)     = h0;
    *(__nv_bfloat162*)(Hd + 2) = h1;
    *(__nv_bfloat162*)(Ld)     = l0;
    *(__nv_bfloat162*)(Ld + 2) = l1;
}
__device__ __forceinline__ void split1s(float v, __nv_bfloat16* H, __nv_bfloat16* L) {
    __nv_bfloat16 hv = __float2bfloat16(v);
    *H = hv;
    *L = __float2bfloat16(v - __bfloat162float(hv));
}

__device__ __forceinline__ unsigned enc_f(float f) {
    unsigned u = __float_as_uint(f);
    return (u & 0x80000000u) ? ~u : (u | 0x80000000u);
}
__device__ __forceinline__ float dec_f(unsigned v) {
    return __uint_as_float((v & 0x80000000u) ? (v ^ 0x80000000u) : ~v);
}

// ---------------- plain split ----------------------------------------------
__global__ void __launch_bounds__(256) split_kernel(
    const float4* __restrict__ src,
    __nv_bfloat16* __restrict__ h, __nv_bfloat16* __restrict__ l, int n4)
{
    int i = blockIdx.x * 256 + threadIdx.x;
    if (i < n4) {
        float4 v = src[i];
        split_store4(h + (size_t)i * 4, l + (size_t)i * 4, v);
    }
}

// ---------------- KV row-concat split ---------------------------------------
__global__ void __launch_bounds__(256) pack_kv(
    const float4* __restrict__ V, const float4* __restrict__ K,
    __nv_bfloat16* __restrict__ h, __nv_bfloat16* __restrict__ l)
{
    constexpr int PER_L = KVROWS * (Dc / 4);
    int i = blockIdx.x * 256 + threadIdx.x;
    if (i >= Lc * PER_L) return;
    const int lay = i / PER_L;
    const int rem = i % PER_L;
    const int row = rem >> 7;
    const int c4  = rem & 127;
    float4 v = (row < YROWS)
        ? V[((size_t)lay * YROWS + row) * 128 + c4]
        : K[((size_t)lay * (Hc * Qc) + row - YROWS) * 128 + c4];
    split_store4(h + (size_t)i * 4, l + (size_t)i * 4, v);
}

// ---------------- X transpose + split (init only) ---------------------------
__global__ void __launch_bounds__(256) tsplit_generic(
    const float* __restrict__ src,
    __nv_bfloat16* __restrict__ dH, __nv_bfloat16* __restrict__ dL,
    float* __restrict__ copyT, int R, int C)
{
    __shared__ float t[32][33];
    const size_t bo = (size_t)blockIdx.z * R * C;
    const int tx = threadIdx.x, ty = threadIdx.y;
    const int x  = blockIdx.x * 32 + tx;
    const int y0 = blockIdx.y * 32;
#pragma unroll
    for (int j = 0; j < 4; j++)
        t[ty + j * 8][tx] = src[bo + (size_t)(y0 + ty + j * 8) * C + x];
    __syncthreads();
#pragma unroll
    for (int j = 0; j < 4; j++) {
        const int k = blockIdx.x * 32 + ty + j * 8;
        const int r = y0 + tx;
        const float v = t[tx][ty + j * 8];
        const size_t di = bo + (size_t)k * R + r;
        split1s(v, dH + di, dL + di);
        if (copyT) copyT[di] = v;
    }
}

// ---------------- final transpose: Xt[n][d] -> out[d][n] --------------------
__global__ void __launch_bounds__(256) tfinal(
    const float* __restrict__ Xt, float* __restrict__ out)
{
    __shared__ float t[32][33];
    const int tx = threadIdx.x, ty = threadIdx.y;
    const int x  = blockIdx.x * 32 + tx;
    const int y0 = blockIdx.y * 32;
#pragma unroll
    for (int j = 0; j < 4; j++)
        t[ty + j * 8][tx] = Xt[(size_t)(y0 + ty + j * 8) * Dc + x];
    __syncthreads();
#pragma unroll
    for (int j = 0; j < 4; j++) {
        const int d = blockIdx.x * 32 + ty + j * 8;
        const int n = y0 + tx;
        out[(size_t)d * Nc + n] = t[tx][ty + j * 8];
    }
}

// ============ bf16-plane 3x GEMM: C[m][n] = sum_k A[m][k]*B[n][k] ==========
// A:[M,K] act planes row-major; B:[N,K] weight planes row-major (col_major
// fragments = implicit transpose). cp.async S-stage pipeline.
// mode bits: 1=relu(+col bias), 2=residual(+col bias), 4=write fp32 C,
//            8=write h+l planes.
// mode==64 -> KV: cols < YROWS fp32 store (pitch YROWS); cols >= YROWS emit
//            h/l planes (pitch 256) at col-YROWS.
template<int BM, int BN, int WM, int WN, int S, int MINB>
__global__ void __launch_bounds__(WM * WN * 32, MINB) bf16_gemm(
    const __nv_bfloat16* __restrict__ Ah, const __nv_bfloat16* __restrict__ Al,
    const __nv_bfloat16* __restrict__ Bh, const __nv_bfloat16* __restrict__ Bl,
    float* __restrict__ C,
    __nv_bfloat16* __restrict__ Ch, __nv_bfloat16* __restrict__ Cl,
    int M, int N, int K,
    const float* __restrict__ bias, const float* __restrict__ R, int mode)
{
    constexpr int TH = WM * WN * 32;
    constexpr int BK = 32;
    constexpr int AP = 40;
    constexpr int BKP = 40;
    constexpr int ABYT = BM * AP * 2;
    constexpr int BBYT = BN * BKP * 2;
    constexpr int STG = 2 * ABYT + 2 * BBYT;
    constexpr int MF = BM / (WM * 16);
    constexpr int NF = BN / (WN * 16);
    constexpr int AIT = BM * (BK / 8) / TH;
    constexpr int BIT = BN * (BK / 8) / TH;

    extern __shared__ char sm[];
    const int tid = threadIdx.x, w = tid >> 5;
    const int bm = blockIdx.y * BM;
    const int bn = blockIdx.x * BN;
    const int wm0 = (w % WM) * (MF * 16);
    const int wn0 = (w / WM) * (NF * 16);
    const int KT = K / BK;

    auto issue = [&](int tile) {
        const int k0 = tile * BK;
        char* st = sm + (tile % S) * STG;
        __nv_bfloat16* sAh = (__nv_bfloat16*)st;
        __nv_bfloat16* sAl = (__nv_bfloat16*)(st + ABYT);
        __nv_bfloat16* sBh = (__nv_bfloat16*)(st + 2 * ABYT);
        __nv_bfloat16* sBl = (__nv_bfloat16*)(st + 2 * ABYT + BBYT);
#pragma unroll
        for (int p = 0; p < AIT; p++) {
            const int c = tid + p * TH;
            const int r = c >> 2, c8 = (c & 3) * 8;
            cp16(sAh + r * AP + c8, Ah + (size_t)(bm + r) * K + k0 + c8);
            cp16(sAl + r * AP + c8, Al + (size_t)(bm + r) * K + k0 + c8);
        }
#pragma unroll
        for (int p = 0; p < BIT; p++) {
            const int c = tid + p * TH;
            const int r = c >> 2, c8 = (c & 3) * 8;
            cp16(sBh + r * BKP + c8, Bh + (size_t)(bn + r) * K + k0 + c8);
            cp16(sBl + r * BKP + c8, Bl + (size_t)(bn + r) * K + k0 + c8);
        }
    };

    wmma::fragment<wmma::accumulator, 16, 16, 16, float> acc[MF][NF];
#pragma unroll
    for (int i = 0; i < MF; i++)
#pragma unroll
        for (int j = 0; j < NF; j++) wmma::fill_fragment(acc[i][j], 0.f);

#pragma unroll
    for (int t = 0; t < S - 1; t++) {
        if (t < KT) issue(t);
        cp_commit();
    }

#pragma unroll 1
    for (int kt = 0; kt < KT; kt++) {
        cp_wait<S - 2>();
        __syncthreads();
        if (kt + S - 1 < KT) issue(kt + S - 1);
        cp_commit();

        char* st = sm + (kt % S) * STG;
        const __nv_bfloat16* sAh = (const __nv_bfloat16*)st;
        const __nv_bfloat16* sAl = (const __nv_bfloat16*)(st + ABYT);
        const __nv_bfloat16* sBh = (const __nv_bfloat16*)(st + 2 * ABYT);
        const __nv_bfloat16* sBl = (const __nv_bfloat16*)(st + 2 * ABYT + BBYT);

#pragma unroll
        for (int kks = 0; kks < 2; kks++) {
            const int kk = kks * 16;
            wmma::fragment<wmma::matrix_a, 16, 16, 16, __nv_bfloat16, wmma::row_major> fAh[MF];
            wmma::fragment<wmma::matrix_b, 16, 16, 16, __nv_bfloat16, wmma::col_major> fBh[NF];
#pragma unroll
            for (int i = 0; i < MF; i++)
                wmma::load_matrix_sync(fAh[i], sAh + (wm0 + i * 16) * AP + kk, AP);
#pragma unroll
            for (int j = 0; j < NF; j++)
                wmma::load_matrix_sync(fBh[j], sBh + (wn0 + j * 16) * BKP + kk, BKP);
#pragma unroll
            for (int i = 0; i < MF; i++)
#pragma unroll
                for (int j = 0; j < NF; j++)
                    wmma::mma_sync(acc[i][j], fAh[i], fBh[j], acc[i][j]);
            {
                wmma::fragment<wmma::matrix_b, 16, 16, 16, __nv_bfloat16, wmma::col_major> fBl[NF];
#pragma unroll
                for (int j = 0; j < NF; j++)
                    wmma::load_matrix_sync(fBl[j], sBl + (wn0 + j * 16) * BKP + kk, BKP);
#pragma unroll
                for (int i = 0; i < MF; i++)
#pragma unroll
                    for (int j = 0; j < NF; j++)
                        wmma::mma_sync(acc[i][j], fAh[i], fBl[j], acc[i][j]);
            }
            {
                wmma::fragment<wmma::matrix_a, 16, 16, 16, __nv_bfloat16, wmma::row_major> fAl[MF];
#pragma unroll
                for (int i = 0; i < MF; i++)
                    wmma::load_matrix_sync(fAl[i], sAl + (wm0 + i * 16) * AP + kk, AP);
#pragma unroll
                for (int i = 0; i < MF; i++)
#pragma unroll
                    for (int j = 0; j < NF; j++)
                        wmma::mma_sync(acc[i][j], fAl[i], fBh[j], acc[i][j]);
            }
        }
    }

    if (mode == 64) {
        if (bn < YROWS) {
#pragma unroll
            for (int i = 0; i < MF; i++)
#pragma unroll
                for (int j = 0; j < NF; j++)
                    wmma::store_matrix_sync(
                        &C[(size_t)(bm + wm0 + i * 16) * YROWS + bn + wn0 + j * 16],
                        acc[i][j], YROWS, wmma::mem_row_major);
        } else {
            __syncthreads();
            float* cs = (float*)sm;
#pragma unroll
            for (int i = 0; i < MF; i++)
#pragma unroll
                for (int j = 0; j < NF; j++)
                    wmma::store_matrix_sync(
                        cs + (size_t)(wm0 + i * 16) * BN + wn0 + j * 16,
                        acc[i][j], BN, wmma::mem_row_major);
            __syncthreads();
            constexpr int CIT2 = BM * BN / 4 / TH;
#pragma unroll
            for (int p = 0; p < CIT2; p++) {
                const int id = tid + p * TH;
                const int row = id / (BN / 4), c4 = id % (BN / 4);
                float4 v = ((const float4*)cs)[id];
                const int gr = bm + row;
                const int gcl = bn - YROWS + c4 * 4;
                split_store4(Ch + (size_t)gr * 256 + gcl,
                             Cl + (size_t)gr * 256 + gcl, v);
            }
        }
        return;
    }

    __syncthreads();
    float* cs = (float*)sm;
#pragma unroll
    for (int i = 0; i < MF; i++)
#pragma unroll
        for (int j = 0; j < NF; j++)
            wmma::store_matrix_sync(cs + (size_t)(wm0 + i * 16) * BN + wn0 + j * 16,
                                    acc[i][j], BN, wmma::mem_row_major);
    __syncthreads();

    constexpr int CIT = BM * BN / 4 / TH;
#pragma unroll
    for (int p = 0; p < CIT; p++) {
        const int id = tid + p * TH;
        const int row = id / (BN / 4), c4 = id % (BN / 4);
        float4 v = ((const float4*)cs)[id];
        const int gr = bm + row;
        const int gc = bn + c4 * 4;
        if (mode & 3) {
            float4 bv = *(const float4*)&bias[gc];
            v.x += bv.x; v.y += bv.y; v.z += bv.z; v.w += bv.w;
        }
        if (mode & 1) {
            v.x = fmaxf(v.x, 0.f); v.y = fmaxf(v.y, 0.f);
            v.z = fmaxf(v.z, 0.f); v.w = fmaxf(v.w, 0.f);
        }
        if (mode & 2) {
            float4 r4 = *(const float4*)&R[(size_t)gr * N + gc];
            v.x += r4.x; v.y += r4.y; v.z += r4.z; v.w += r4.w;
        }
        if (mode & 4) *(float4*)&C[(size_t)gr * N + gc] = v;
        if (mode & 8) split_store4(Ch + (size_t)gr * N + gc,
                                   Cl + (size_t)gr * N + gc, v);
    }
}

// ====== fused gram + argmax + scatter (N-major, coalesced) ================
#define CAND 96
__global__ void __launch_bounds__(256) gram_argmax_scatter(
    const __nv_bfloat16* __restrict__ KXh, const __nv_bfloat16* __restrict__ KXl,
    const float* __restrict__ Y, float* __restrict__ attn)
{
    constexpr int AP = 72, BP = 72, CP = 132;
    extern __shared__ char sm[];
    __nv_bfloat16* aH = (__nv_bfloat16*)sm;
    __nv_bfloat16* aL = (__nv_bfloat16*)(sm + 9216);
    float*    Cs   = (float*)(sm + 92160);
    unsigned* rm   = (unsigned*)(sm + 125952);
    int*      cnt  = (int*)(sm + 126208);
    float*    wrow = (float*)(sm + 126464);
    int*      cm   = (int*)(sm + 126720);
    float*    csv  = (float*)(sm + 151296);

    const int h  = blockIdx.y;
    const int r0 = blockIdx.x * 64;
    const int co = h * 64;
    const int tid = threadIdx.x, w = tid >> 5, lane = tid & 31;
    const int wm0 = (w & 1) * 32, wn0 = (w >> 1) * 32;

    if (tid < 64) { rm[tid] = enc_f(-1e30f); cnt[tid] = 0; }

    auto issueB = [&](int mt, int s) {
        const int m0 = mt * 128;
        __nv_bfloat16* bH = (__nv_bfloat16*)(sm + 18432 + s * 36864);
        __nv_bfloat16* bL = (__nv_bfloat16*)(sm + 18432 + s * 36864 + 18432);
#pragma unroll
        for (int p = 0; p < 4; p++) {
            const int c = tid + p * 256;
            const int r = c >> 3, c8 = (c & 7) * 8;
            cp16(bH + r * BP + c8, KXh + (size_t)(m0 + r) * 256 + co + c8);
            cp16(bL + r * BP + c8, KXl + (size_t)(m0 + r) * 256 + co + c8);
        }
    };

#pragma unroll
    for (int p = 0; p < 2; p++) {
        const int c = tid + p * 256;
        const int r = c >> 3, c8 = (c & 7) * 8;
        cp16(aH + r * AP + c8, KXh + (size_t)(r0 + r) * 256 + co + c8);
        cp16(aL + r * AP + c8, KXl + (size_t)(r0 + r) * 256 + co + c8);
    }
    issueB(0, 0);
    cp_commit();

    for (int mt = 0; mt < Nc / 128; mt++) {
        if (mt + 1 < Nc / 128) issueB(mt + 1, (mt + 1) & 1);
        cp_commit();
        cp_wait<1>();
        __syncthreads();

        const __nv_bfloat16* bH = (const __nv_bfloat16*)(sm + 18432 + (mt & 1) * 36864);
        const __nv_bfloat16* bL = bH + 18432 / 2;

        wmma::fragment<wmma::accumulator, 16, 16, 16, float> acc[2][2];
#pragma unroll
        for (int i = 0; i < 2; i++)
#pragma unroll
            for (int j = 0; j < 2; j++) wmma::fill_fragment(acc[i][j], 0.f);

#pragma unroll
        for (int kks = 0; kks < 4; kks++) {
            const int kk = kks * 16;
            wmma::fragment<wmma::matrix_a, 16, 16, 16, __nv_bfloat16, wmma::row_major> fAh[2];
            wmma::fragment<wmma::matrix_b, 16, 16, 16, __nv_bfloat16, wmma::col_major> fBh[2];
#pragma unroll
            for (int i = 0; i < 2; i++)
                wmma::load_matrix_sync(fAh[i], aH + (wm0 + i * 16) * AP + kk, AP);
#pragma unroll
            for (int j = 0; j < 2; j++)
                wmma::load_matrix_sync(fBh[j], bH + (wn0 + j * 16) * BP + kk, BP);
#pragma unroll
            for (int i = 0; i < 2; i++)
#pragma unroll
                for (int j = 0; j < 2; j++)
                    wmma::mma_sync(acc[i][j], fAh[i], fBh[j], acc[i][j]);
            {
                wmma::fragment<wmma::matrix_b, 16, 16, 16, __nv_bfloat16, wmma::col_major> fBl[2];
#pragma unroll
                for (int j = 0; j < 2; j++)
                    wmma::load_matrix_sync(fBl[j], bL + (wn0 + j * 16) * BP + kk, BP);
#pragma unroll
                for (int i = 0; i < 2; i++)
#pragma unroll
                    for (int j = 0; j < 2; j++)
                        wmma::mma_sync(acc[i][j], fAh[i], fBl[j], acc[i][j]);
            }
            {
                wmma::fragment<wmma::matrix_a, 16, 16, 16, __nv_bfloat16, wmma::row_major> fAl[2];
#pragma unroll
                for (int i = 0; i < 2; i++)
                    wmma::load_matrix_sync(fAl[i], aL + (wm0 + i * 16) * AP + kk, AP);
#pragma unroll
                for (int i = 0; i < 2; i++)
#pragma unroll
                    for (int j = 0; j < 2; j++)
                        wmma::mma_sync(acc[i][j], fAl[i], fBh[j], acc[i][j]);
            }
        }
#pragma unroll
        for (int i = 0; i < 2; i++)
#pragma unroll
            for (int j = 0; j < 2; j++)
                wmma::store_matrix_sync(Cs + (wm0 + i * 16) * CP + wn0 + j * 16,
                                        acc[i][j], CP, wmma::mem_row_major);
        __syncthreads();

        const int r = tid >> 2;
        const int c0 = (tid & 3) * 32;
        float tm = -1e30f;
#pragma unroll
        for (int c = 0; c < 32; c++) tm = fmaxf(tm, Cs[r * CP + c0 + c]);
        tm = fmaxf(tm, __shfl_xor_sync(0xffffffffu, tm, 1, 4));
        tm = fmaxf(tm, __shfl_xor_sync(0xffffffffu, tm, 2, 4));
        if ((tid & 3) == 0) atomicMax(&rm[r], enc_f(tm));
        __syncthreads();

        const float thr = dec_f(rm[r]) - 0.5f;
        const int m0 = mt * 128;
#pragma unroll
        for (int c = 0; c < 32; c++) {
            const float v = Cs[r * CP + c0 + c];
            if (v >= thr) {
                int pos = atomicAdd(&cnt[r], 1);
                if (pos < CAND) {
                    cm[r * CAND + pos]  = m0 + c0 + c;
                    csv[r * CAND + pos] = v;
                }
            }
        }
        __syncthreads();
    }

    if (tid < 64) {
        const float fmax = dec_f(rm[tid]);
        const float thrF = fmax - 0.5f;
        const int nc = cnt[tid] < CAND ? cnt[tid] : CAND;
        int hits = 0;
        for (int j = 0; j < nc; j++) {
            if (csv[tid * CAND + j] >= thrF) {
                cm[tid * CAND + hits] = cm[tid * CAND + j];
                hits++;
            }
        }
        cnt[tid] = hits;
        wrow[tid] = (fabsf(fmax) > 0.5f && hits > 0) ? 1.f / (float)hits : 0.f;
    }
    __syncthreads();

    for (int rr = 0; rr < 8; rr++) {
        const int r = w * 8 + rr;
        const float wv = wrow[r];
        const int hits = cnt[r];
        if (wv == 0.f || hits == 0) continue;
        const int n = r0 + r;
        const float* yrow = Y + (size_t)n * YROWS + h * Dc;
        float yv[16];
#pragma unroll
        for (int p = 0; p < 16; p++)
            yv[p] = wv * yrow[lane + p * 32];
        for (int j = 0; j < hits; j++) {
            float* arow = attn + (size_t)cm[r * CAND + j] * Dc;
#pragma unroll
            for (int p = 0; p < 16; p++)
                atomicAdd(&arow[lane + p * 32], yv[p]);
        }
    }
}

// --------------------------------------------------------------------------
extern "C" void kernel_launch(void* const* d_in, const int* in_sizes, int n_in,
                              void* d_out, int out_size)
{
    const float* X  = (const float*)d_in[0];
    const float* Kp = (const float*)d_in[1];
    const float* Vp = (const float*)d_in[2];
    const float* W1 = (const float*)d_in[3];
    const float* b1 = (const float*)d_in[4];
    const float* W2 = (const float*)d_in[5];
    const float* b2 = (const float*)d_in[6];

    float *gX, *gAttn, *gY;
    __nv_bfloat16 *gKVh, *gKVl, *gW1h, *gW1l, *gW2h, *gW2l;
    __nv_bfloat16 *gXh, *gXl, *gAth, *gAtl, *gF1h, *gF1l, *gKXh, *gKXl;
    cudaGetSymbolAddress((void**)&gX,   g_X);
    cudaGetSymbolAddress((void**)&gAttn,g_attn);
    cudaGetSymbolAddress((void**)&gY,   g_Y);
    cudaGetSymbolAddress((void**)&gKVh, g_KVh);  cudaGetSymbolAddress((void**)&gKVl, g_KVl);
    cudaGetSymbolAddress((void**)&gW1h, g_W1h);  cudaGetSymbolAddress((void**)&gW1l, g_W1l);
    cudaGetSymbolAddress((void**)&gW2h, g_W2h);  cudaGetSymbolAddress((void**)&gW2l, g_W2l);
    cudaGetSymbolAddress((void**)&gXh,  g_Xh);   cudaGetSymbolAddress((void**)&gXl,  g_Xl);
    cudaGetSymbolAddress((void**)&gAth, g_Ath);  cudaGetSymbolAddress((void**)&gAtl, g_Atl);
    cudaGetSymbolAddress((void**)&gF1h, g_F1h);  cudaGetSymbolAddress((void**)&gF1l, g_F1l);
    cudaGetSymbolAddress((void**)&gKXh, g_KXh);  cudaGetSymbolAddress((void**)&gKXl, g_KXl);

    const int SMBIG = 2 * (2 * 128 * 40 * 2 + 2 * 128 * 40 * 2);  // 81920 (S=2)
    const int SMF2  = 4 * (2 *  64 * 40 * 2 + 2 * 128 * 40 * 2);  // 122880 (S=4)
    const int SMGR  = 175872;
    cudaFuncSetAttribute(bf16_gemm<128, 128, 4, 4, 2, 2>,
                         cudaFuncAttributeMaxDynamicSharedMemorySize, SMBIG);
    cudaFuncSetAttribute(bf16_gemm<64, 128, 2, 4, 4, 1>,
                         cudaFuncAttributeMaxDynamicSharedMemorySize, SMF2);
    cudaFuncSetAttribute(gram_argmax_scatter,
                         cudaFuncAttributeMaxDynamicSharedMemorySize, SMGR);

    {
        const int nKV = Lc * KVROWS * Dc / 4;
        const int nW  = Lc * DFFc * Dc / 4;
        pack_kv<<<(nKV + 255) / 256, 256>>>((const float4*)Vp, (const float4*)Kp,
                                            gKVh, gKVl);
        split_kernel<<<(nW + 255) / 256, 256>>>((const float4*)W1, gW1h, gW1l, nW);
        split_kernel<<<(nW + 255) / 256, 256>>>((const float4*)W2, gW2h, gW2l, nW);
        tsplit_generic<<<dim3(2048 / 32, 512 / 32, 1), dim3(32, 8)>>>(
            X, gXh, gXl, gAttn, Dc, Nc);
    }

    for (int l = 0; l < Lc; l++) {
        const float* b1l = b1 + (size_t)l * DFFc;
        const float* b2l = b2 + (size_t)l * Dc;
        const bool last = (l == Lc - 1);

        // 1) [Y | KXt] = Xt @ KV^T  (mode 64, 288 blocks, 512 thr, 2/SM)
        bf16_gemm<128, 128, 4, 4, 2, 2><<<dim3(KVROWS / 128, Nc / 128, 1), 512, SMBIG>>>(
            gXh, gXl,
            gKVh + (size_t)l * KVROWS * Dc, gKVl + (size_t)l * KVROWS * Dc,
            gY, gKXh, gKXl, Nc, KVROWS, Dc, nullptr, nullptr, 64);

        // 2) fused gram+argmax+scatter
        gram_argmax_scatter<<<dim3(Nc / 64, Hc), 256, SMGR>>>(gKXh, gKXl, gY, gAttn);

        // 3) attn_t planes
        split_kernel<<<(Nc * Dc / 4 + 255) / 256, 256>>>(
            (const float4*)gAttn, gAth, gAtl, Nc * Dc / 4);

        // 4) ff1_t planes = relu(attn_t @ W1^T + b1[col])  (mode 9, 512 thr)
        bf16_gemm<128, 128, 4, 4, 2, 2><<<dim3(DFFc / 128, Nc / 128, 1), 512, SMBIG>>>(
            gAth, gAtl,
            gW1h + (size_t)l * DFFc * Dc, gW1l + (size_t)l * DFFc * Dc,
            nullptr, gF1h, gF1l, Nc, DFFc, Dc, b1l, nullptr, 9);

        // 5) X_t = attn_t + ff1_t @ W2^T + b2[col]
        if (last) {
            bf16_gemm<64, 128, 2, 4, 4, 1><<<dim3(Dc / 128, Nc / 64, 1), 256, SMF2>>>(
                gF1h, gF1l,
                gW2h + (size_t)l * Dc * DFFc, gW2l + (size_t)l * Dc * DFFc,
                gX, nullptr, nullptr, Nc, Dc, DFFc, b2l, gAttn, 6);
        } else {
            bf16_gemm<64, 128, 2, 4, 4, 1><<<dim3(Dc / 128, Nc / 64, 1), 256, SMF2>>>(
                gF1h, gF1l,
                gW2h + (size_t)l * Dc * DFFc, gW2l + (size_t)l * Dc * DFFc,
                gAttn, gXh, gXl, Nc, Dc, DFFc, b2l, gAttn, 14);
        }
    }

    // final transpose X_t[n][d] -> d_out[d][n]
    tfinal<<<dim3(Dc / 32, Nc / 32, 1), dim3(32, 8)>>>(gX, (float*)d_out);
}

// round 16
// speedup vs baseline: 1.0886x; 1.0886x over previous
#include <cuda_runtime.h>
#include <cuda_bf16.h>
#include <mma.h>
#include <cstdint>

using namespace nvcuda;

#define Lc   8
#define Hc   4
#define Qc   64
#define Dc   512
#define Nc   2048
#define DFFc 2048
#define KVROWS (Hc * Dc + Hc * Qc)   // 2304 output cols: Y then KX
#define YROWS  (Hc * Dc)             // 2048

// ---------------- device scratch (no allocations allowed) ----------------
__device__ float g_X[Nc * Dc];
__device__ float g_attn[Nc * Dc];
__device__ float g_Y[Nc * YROWS];
__device__ __nv_bfloat16 g_KVh[Lc * KVROWS * Dc], g_KVl[Lc * KVROWS * Dc];
__device__ __nv_bfloat16 g_W1h[Lc * DFFc * Dc],   g_W1l[Lc * DFFc * Dc];
__device__ __nv_bfloat16 g_W2h[Lc * Dc * DFFc],   g_W2l[Lc * Dc * DFFc];
__device__ __nv_bfloat16 g_Xh[Nc * Dc],           g_Xl[Nc * Dc];
__device__ __nv_bfloat16 g_Ath[Nc * Dc],          g_Atl[Nc * Dc];
__device__ __nv_bfloat16 g_F1h[Nc * DFFc],        g_F1l[Nc * DFFc];
__device__ __nv_bfloat16 g_KXh[Nc * 256],         g_KXl[Nc * 256];

// ---------------- helpers --------------------------------------------------
__device__ __forceinline__ uint32_t smem_u32(const void* p) {
    uint32_t a;
    asm("{ .reg .u64 t; cvta.to.shared.u64 t, %1; cvt.u32.u64 %0, t; }"
        : "=r"(a) : "l"(p));
    return a;
}
__device__ __forceinline__ void cp16(void* s, const void* g) {
    asm volatile("cp.async.cg.shared.global [%0], [%1], 16;"
                 :: "r"(smem_u32(s)), "l"(g) : "memory");
}
__device__ __forceinline__ void cp_commit() {
    asm volatile("cp.async.commit_group;" ::: "memory");
}
template<int N> __device__ __forceinline__ void cp_wait() {
    asm volatile("cp.async.wait_group %0;" :: "n"(N) : "memory");
}

__device__ __forceinline__ void split_store4(__nv_bfloat16* __restrict__ Hd,
                                             __nv_bfloat16* __restrict__ Ld,
                                             float4 v)
{
    __nv_bfloat162 h0 = __floats2bfloat162_rn(v.x, v.y);
    __nv_bfloat162 h1 = __floats2bfloat162_rn(v.z, v.w);
    float2 f0 = __bfloat1622float2(h0);
    float2 f1 = __bfloat1622float2(h1);
    __nv_bfloat162 l0 = __floats2bfloat162_rn(v.x - f0.x, v.y - f0.y);
    __nv_bfloat162 l1 = __floats2bfloat162_rn(v.z - f1.x, v.w - f1.y);
    *(__nv_bfloat162*)(Hd)     = h0;
    *(__nv_bfloat162*)(Hd + 2) = h1;
    *(__nv_bfloat162*)(Ld)     = l0;
    *(__nv_bfloat162*)(Ld + 2) = l1;
}
__device__ __forceinline__ void split1s(float v, __nv_bfloat16* H, __nv_bfloat16* L) {
    __nv_bfloat16 hv = __float2bfloat16(v);
    *H = hv;
    *L = __float2bfloat16(v - __bfloat162float(hv));
}

__device__ __forceinline__ unsigned enc_f(float f) {
    unsigned u = __float_as_uint(f);
    return (u & 0x80000000u) ? ~u : (u | 0x80000000u);
}
__device__ __forceinline__ float dec_f(unsigned v) {
    return __uint_as_float((v & 0x80000000u) ? (v ^ 0x80000000u) : ~v);
}

// ---------------- plain split ----------------------------------------------
__global__ void __launch_bounds__(256) split_kernel(
    const float4* __restrict__ src,
    __nv_bfloat16* __restrict__ h, __nv_bfloat16* __restrict__ l, int n4)
{
    int i = blockIdx.x * 256 + threadIdx.x;
    if (i < n4) {
        float4 v = src[i];
        split_store4(h + (size_t)i * 4, l + (size_t)i * 4, v);
    }
}

// ---------------- KV row-concat split ---------------------------------------
__global__ void __launch_bounds__(256) pack_kv(
    const float4* __restrict__ V, const float4* __restrict__ K,
    __nv_bfloat16* __restrict__ h, __nv_bfloat16* __restrict__ l)
{
    constexpr int PER_L = KVROWS * (Dc / 4);
    int i = blockIdx.x * 256 + threadIdx.x;
    if (i >= Lc * PER_L) return;
    const int lay = i / PER_L;
    const int rem = i % PER_L;
    const int row = rem >> 7;
    const int c4  = rem & 127;
    float4 v = (row < YROWS)
        ? V[((size_t)lay * YROWS + row) * 128 + c4]
        : K[((size_t)lay * (Hc * Qc) + row - YROWS) * 128 + c4];
    split_store4(h + (size_t)i * 4, l + (size_t)i * 4, v);
}

// ---------------- X transpose + split (init only) ---------------------------
__global__ void __launch_bounds__(256) tsplit_generic(
    const float* __restrict__ src,
    __nv_bfloat16* __restrict__ dH, __nv_bfloat16* __restrict__ dL,
    float* __restrict__ copyT, int R, int C)
{
    __shared__ float t[32][33];
    const size_t bo = (size_t)blockIdx.z * R * C;
    const int tx = threadIdx.x, ty = threadIdx.y;
    const int x  = blockIdx.x * 32 + tx;
    const int y0 = blockIdx.y * 32;
#pragma unroll
    for (int j = 0; j < 4; j++)
        t[ty + j * 8][tx] = src[bo + (size_t)(y0 + ty + j * 8) * C + x];
    __syncthreads();
#pragma unroll
    for (int j = 0; j < 4; j++) {
        const int k = blockIdx.x * 32 + ty + j * 8;
        const int r = y0 + tx;
        const float v = t[tx][ty + j * 8];
        const size_t di = bo + (size_t)k * R + r;
        split1s(v, dH + di, dL + di);
        if (copyT) copyT[di] = v;
    }
}

// ---------------- final transpose: Xt[n][d] -> out[d][n] --------------------
__global__ void __launch_bounds__(256) tfinal(
    const float* __restrict__ Xt, float* __restrict__ out)
{
    __shared__ float t[32][33];
    const int tx = threadIdx.x, ty = threadIdx.y;
    const int x  = blockIdx.x * 32 + tx;
    const int y0 = blockIdx.y * 32;
#pragma unroll
    for (int j = 0; j < 4; j++)
        t[ty + j * 8][tx] = Xt[(size_t)(y0 + ty + j * 8) * Dc + x];
    __syncthreads();
#pragma unroll
    for (int j = 0; j < 4; j++) {
        const int d = blockIdx.x * 32 + ty + j * 8;
        const int n = y0 + tx;
        out[(size_t)d * Nc + n] = t[tx][ty + j * 8];
    }
}

// ============ bf16-plane 3x GEMM: C[m][n] = sum_k A[m][k]*B[n][k] ==========
// A:[M,K] act planes row-major; B:[N,K] weight planes row-major (col_major
// fragments = implicit transpose). cp.async S-stage pipeline.
// mode bits: 1=relu(+col bias), 2=residual(+col bias), 4=write fp32 C,
//            8=write h+l planes.
// mode==64 -> KV: cols < YROWS fp32 store (pitch YROWS); cols >= YROWS emit
//            h/l planes (pitch 256) at col-YROWS.
template<int BM, int BN, int WM, int WN, int S, int MINB>
__global__ void __launch_bounds__(WM * WN * 32, MINB) bf16_gemm(
    const __nv_bfloat16* __restrict__ Ah, const __nv_bfloat16* __restrict__ Al,
    const __nv_bfloat16* __restrict__ Bh, const __nv_bfloat16* __restrict__ Bl,
    float* __restrict__ C,
    __nv_bfloat16* __restrict__ Ch, __nv_bfloat16* __restrict__ Cl,
    int M, int N, int K,
    const float* __restrict__ bias, const float* __restrict__ R, int mode)
{
    constexpr int TH = WM * WN * 32;
    constexpr int BK = 32;
    constexpr int AP = 40;
    constexpr int BKP = 40;
    constexpr int ABYT = BM * AP * 2;
    constexpr int BBYT = BN * BKP * 2;
    constexpr int STG = 2 * ABYT + 2 * BBYT;
    constexpr int MF = BM / (WM * 16);
    constexpr int NF = BN / (WN * 16);
    constexpr int AIT = BM * (BK / 8) / TH;
    constexpr int BIT = BN * (BK / 8) / TH;

    extern __shared__ char sm[];
    const int tid = threadIdx.x, w = tid >> 5;
    const int bm = blockIdx.y * BM;
    const int bn = blockIdx.x * BN;
    const int wm0 = (w % WM) * (MF * 16);
    const int wn0 = (w / WM) * (NF * 16);
    const int KT = K / BK;

    auto issue = [&](int tile) {
        const int k0 = tile * BK;
        char* st = sm + (tile % S) * STG;
        __nv_bfloat16* sAh = (__nv_bfloat16*)st;
        __nv_bfloat16* sAl = (__nv_bfloat16*)(st + ABYT);
        __nv_bfloat16* sBh = (__nv_bfloat16*)(st + 2 * ABYT);
        __nv_bfloat16* sBl = (__nv_bfloat16*)(st + 2 * ABYT + BBYT);
#pragma unroll
        for (int p = 0; p < AIT; p++) {
            const int c = tid + p * TH;
            const int r = c >> 2, c8 = (c & 3) * 8;
            cp16(sAh + r * AP + c8, Ah + (size_t)(bm + r) * K + k0 + c8);
            cp16(sAl + r * AP + c8, Al + (size_t)(bm + r) * K + k0 + c8);
        }
#pragma unroll
        for (int p = 0; p < BIT; p++) {
            const int c = tid + p * TH;
            const int r = c >> 2, c8 = (c & 3) * 8;
            cp16(sBh + r * BKP + c8, Bh + (size_t)(bn + r) * K + k0 + c8);
            cp16(sBl + r * BKP + c8, Bl + (size_t)(bn + r) * K + k0 + c8);
        }
    };

    wmma::fragment<wmma::accumulator, 16, 16, 16, float> acc[MF][NF];
#pragma unroll
    for (int i = 0; i < MF; i++)
#pragma unroll
        for (int j = 0; j < NF; j++) wmma::fill_fragment(acc[i][j], 0.f);

#pragma unroll
    for (int t = 0; t < S - 1; t++) {
        if (t < KT) issue(t);
        cp_commit();
    }

#pragma unroll 1
    for (int kt = 0; kt < KT; kt++) {
        cp_wait<S - 2>();
        __syncthreads();
        if (kt + S - 1 < KT) issue(kt + S - 1);
        cp_commit();

        char* st = sm + (kt % S) * STG;
        const __nv_bfloat16* sAh = (const __nv_bfloat16*)st;
        const __nv_bfloat16* sAl = (const __nv_bfloat16*)(st + ABYT);
        const __nv_bfloat16* sBh = (const __nv_bfloat16*)(st + 2 * ABYT);
        const __nv_bfloat16* sBl = (const __nv_bfloat16*)(st + 2 * ABYT + BBYT);

#pragma unroll
        for (int kks = 0; kks < 2; kks++) {
            const int kk = kks * 16;
            wmma::fragment<wmma::matrix_a, 16, 16, 16, __nv_bfloat16, wmma::row_major> fAh[MF];
            wmma::fragment<wmma::matrix_b, 16, 16, 16, __nv_bfloat16, wmma::col_major> fBh[NF];
#pragma unroll
            for (int i = 0; i < MF; i++)
                wmma::load_matrix_sync(fAh[i], sAh + (wm0 + i * 16) * AP + kk, AP);
#pragma unroll
            for (int j = 0; j < NF; j++)
                wmma::load_matrix_sync(fBh[j], sBh + (wn0 + j * 16) * BKP + kk, BKP);
#pragma unroll
            for (int i = 0; i < MF; i++)
#pragma unroll
                for (int j = 0; j < NF; j++)
                    wmma::mma_sync(acc[i][j], fAh[i], fBh[j], acc[i][j]);
            {
                wmma::fragment<wmma::matrix_b, 16, 16, 16, __nv_bfloat16, wmma::col_major> fBl[NF];
#pragma unroll
                for (int j = 0; j < NF; j++)
                    wmma::load_matrix_sync(fBl[j], sBl + (wn0 + j * 16) * BKP + kk, BKP);
#pragma unroll
                for (int i = 0; i < MF; i++)
#pragma unroll
                    for (int j = 0; j < NF; j++)
                        wmma::mma_sync(acc[i][j], fAh[i], fBl[j], acc[i][j]);
            }
            {
                wmma::fragment<wmma::matrix_a, 16, 16, 16, __nv_bfloat16, wmma::row_major> fAl[MF];
#pragma unroll
                for (int i = 0; i < MF; i++)
                    wmma::load_matrix_sync(fAl[i], sAl + (wm0 + i * 16) * AP + kk, AP);
#pragma unroll
                for (int i = 0; i < MF; i++)
#pragma unroll
                    for (int j = 0; j < NF; j++)
                        wmma::mma_sync(acc[i][j], fAl[i], fBh[j], acc[i][j]);
            }
        }
    }

    if (mode == 64) {
        if (bn < YROWS) {
#pragma unroll
            for (int i = 0; i < MF; i++)
#pragma unroll
                for (int j = 0; j < NF; j++)
                    wmma::store_matrix_sync(
                        &C[(size_t)(bm + wm0 + i * 16) * YROWS + bn + wn0 + j * 16],
                        acc[i][j], YROWS, wmma::mem_row_major);
        } else {
            __syncthreads();
            float* cs = (float*)sm;
#pragma unroll
            for (int i = 0; i < MF; i++)
#pragma unroll
                for (int j = 0; j < NF; j++)
                    wmma::store_matrix_sync(
                        cs + (size_t)(wm0 + i * 16) * BN + wn0 + j * 16,
                        acc[i][j], BN, wmma::mem_row_major);
            __syncthreads();
            constexpr int CIT2 = BM * BN / 4 / TH;
#pragma unroll
            for (int p = 0; p < CIT2; p++) {
                const int id = tid + p * TH;
                const int row = id / (BN / 4), c4 = id % (BN / 4);
                float4 v = ((const float4*)cs)[id];
                const int gr = bm + row;
                const int gcl = bn - YROWS + c4 * 4;
                split_store4(Ch + (size_t)gr * 256 + gcl,
                             Cl + (size_t)gr * 256 + gcl, v);
            }
        }
        return;
    }

    __syncthreads();
    float* cs = (float*)sm;
#pragma unroll
    for (int i = 0; i < MF; i++)
#pragma unroll
        for (int j = 0; j < NF; j++)
            wmma::store_matrix_sync(cs + (size_t)(wm0 + i * 16) * BN + wn0 + j * 16,
                                    acc[i][j], BN, wmma::mem_row_major);
    __syncthreads();

    constexpr int CIT = BM * BN / 4 / TH;
#pragma unroll
    for (int p = 0; p < CIT; p++) {
        const int id = tid + p * TH;
        const int row = id / (BN / 4), c4 = id % (BN / 4);
        float4 v = ((const float4*)cs)[id];
        const int gr = bm + row;
        const int gc = bn + c4 * 4;
        if (mode & 3) {
            float4 bv = *(const float4*)&bias[gc];
            v.x += bv.x; v.y += bv.y; v.z += bv.z; v.w += bv.w;
        }
        if (mode & 1) {
            v.x = fmaxf(v.x, 0.f); v.y = fmaxf(v.y, 0.f);
            v.z = fmaxf(v.z, 0.f); v.w = fmaxf(v.w, 0.f);
        }
        if (mode & 2) {
            float4 r4 = *(const float4*)&R[(size_t)gr * N + gc];
            v.x += r4.x; v.y += r4.y; v.z += r4.z; v.w += r4.w;
        }
        if (mode & 4) *(float4*)&C[(size_t)gr * N + gc] = v;
        if (mode & 8) split_store4(Ch + (size_t)gr * N + gc,
                                   Cl + (size_t)gr * N + gc, v);
    }
}

// ====== fused gram + argmax + scatter (N-major, coalesced) ================
#define CAND 96
__global__ void __launch_bounds__(256) gram_argmax_scatter(
    const __nv_bfloat16* __restrict__ KXh, const __nv_bfloat16* __restrict__ KXl,
    const float* __restrict__ Y, float* __restrict__ attn)
{
    constexpr int AP = 72, BP = 72, CP = 132;
    extern __shared__ char sm[];
    __nv_bfloat16* aH = (__nv_bfloat16*)sm;
    __nv_bfloat16* aL = (__nv_bfloat16*)(sm + 9216);
    float*    Cs   = (float*)(sm + 92160);
    unsigned* rm   = (unsigned*)(sm + 125952);
    int*      cnt  = (int*)(sm + 126208);
    float*    wrow = (float*)(sm + 126464);
    int*      cm   = (int*)(sm + 126720);
    float*    csv  = (float*)(sm + 151296);

    const int h  = blockIdx.y;
    const int r0 = blockIdx.x * 64;
    const int co = h * 64;
    const int tid = threadIdx.x, w = tid >> 5, lane = tid & 31;
    const int wm0 = (w & 1) * 32, wn0 = (w >> 1) * 32;

    if (tid < 64) { rm[tid] = enc_f(-1e30f); cnt[tid] = 0; }

    auto issueB = [&](int mt, int s) {
        const int m0 = mt * 128;
        __nv_bfloat16* bH = (__nv_bfloat16*)(sm + 18432 + s * 36864);
        __nv_bfloat16* bL = (__nv_bfloat16*)(sm + 18432 + s * 36864 + 18432);
#pragma unroll
        for (int p = 0; p < 4; p++) {
            const int c = tid + p * 256;
            const int r = c >> 3, c8 = (c & 7) * 8;
            cp16(bH + r * BP + c8, KXh + (size_t)(m0 + r) * 256 + co + c8);
            cp16(bL + r * BP + c8, KXl + (size_t)(m0 + r) * 256 + co + c8);
        }
    };

#pragma unroll
    for (int p = 0; p < 2; p++) {
        const int c = tid + p * 256;
        const int r = c >> 3, c8 = (c & 7) * 8;
        cp16(aH + r * AP + c8, KXh + (size_t)(r0 + r) * 256 + co + c8);
        cp16(aL + r * AP + c8, KXl + (size_t)(r0 + r) * 256 + co + c8);
    }
    issueB(0, 0);
    cp_commit();

    for (int mt = 0; mt < Nc / 128; mt++) {
        if (mt + 1 < Nc / 128) issueB(mt + 1, (mt + 1) & 1);
        cp_commit();
        cp_wait<1>();
        __syncthreads();

        const __nv_bfloat16* bH = (const __nv_bfloat16*)(sm + 18432 + (mt & 1) * 36864);
        const __nv_bfloat16* bL = bH + 18432 / 2;

        wmma::fragment<wmma::accumulator, 16, 16, 16, float> acc[2][2];
#pragma unroll
        for (int i = 0; i < 2; i++)
#pragma unroll
            for (int j = 0; j < 2; j++) wmma::fill_fragment(acc[i][j], 0.f);

#pragma unroll
        for (int kks = 0; kks < 4; kks++) {
            const int kk = kks * 16;
            wmma::fragment<wmma::matrix_a, 16, 16, 16, __nv_bfloat16, wmma::row_major> fAh[2];
            wmma::fragment<wmma::matrix_b, 16, 16, 16, __nv_bfloat16, wmma::col_major> fBh[2];
#pragma unroll
            for (int i = 0; i < 2; i++)
                wmma::load_matrix_sync(fAh[i], aH + (wm0 + i * 16) * AP + kk, AP);
#pragma unroll
            for (int j = 0; j < 2; j++)
                wmma::load_matrix_sync(fBh[j], bH + (wn0 + j * 16) * BP + kk, BP);
#pragma unroll
            for (int i = 0; i < 2; i++)
#pragma unroll
                for (int j = 0; j < 2; j++)
                    wmma::mma_sync(acc[i][j], fAh[i], fBh[j], acc[i][j]);
            {
                wmma::fragment<wmma::matrix_b, 16, 16, 16, __nv_bfloat16, wmma::col_major> fBl[2];
#pragma unroll
                for (int j = 0; j < 2; j++)
                    wmma::load_matrix_sync(fBl[j], bL + (wn0 + j * 16) * BP + kk, BP);
#pragma unroll
                for (int i = 0; i < 2; i++)
#pragma unroll
                    for (int j = 0; j < 2; j++)
                        wmma::mma_sync(acc[i][j], fAh[i], fBl[j], acc[i][j]);
            }
            {
                wmma::fragment<wmma::matrix_a, 16, 16, 16, __nv_bfloat16, wmma::row_major> fAl[2];
#pragma unroll
                for (int i = 0; i < 2; i++)
                    wmma::load_matrix_sync(fAl[i], aL + (wm0 + i * 16) * AP + kk, AP);
#pragma unroll
                for (int i = 0; i < 2; i++)
#pragma unroll
                    for (int j = 0; j < 2; j++)
                        wmma::mma_sync(acc[i][j], fAl[i], fBh[j], acc[i][j]);
            }
        }
#pragma unroll
        for (int i = 0; i < 2; i++)
#pragma unroll
            for (int j = 0; j < 2; j++)
                wmma::store_matrix_sync(Cs + (wm0 + i * 16) * CP + wn0 + j * 16,
                                        acc[i][j], CP, wmma::mem_row_major);
        __syncthreads();

        const int r = tid >> 2;
        const int c0 = (tid & 3) * 32;
        float tm = -1e30f;
#pragma unroll
        for (int c = 0; c < 32; c++) tm = fmaxf(tm, Cs[r * CP + c0 + c]);
        tm = fmaxf(tm, __shfl_xor_sync(0xffffffffu, tm, 1, 4));
        tm = fmaxf(tm, __shfl_xor_sync(0xffffffffu, tm, 2, 4));
        if ((tid & 3) == 0) atomicMax(&rm[r], enc_f(tm));
        __syncthreads();

        const float thr = dec_f(rm[r]) - 0.5f;
        const int m0 = mt * 128;
#pragma unroll
        for (int c = 0; c < 32; c++) {
            const float v = Cs[r * CP + c0 + c];
            if (v >= thr) {
                int pos = atomicAdd(&cnt[r], 1);
                if (pos < CAND) {
                    cm[r * CAND + pos]  = m0 + c0 + c;
                    csv[r * CAND + pos] = v;
                }
            }
        }
        __syncthreads();
    }

    if (tid < 64) {
        const float fmax = dec_f(rm[tid]);
        const float thrF = fmax - 0.5f;
        const int nc = cnt[tid] < CAND ? cnt[tid] : CAND;
        int hits = 0;
        for (int j = 0; j < nc; j++) {
            if (csv[tid * CAND + j] >= thrF) {
                cm[tid * CAND + hits] = cm[tid * CAND + j];
                hits++;
            }
        }
        cnt[tid] = hits;
        wrow[tid] = (fabsf(fmax) > 0.5f && hits > 0) ? 1.f / (float)hits : 0.f;
    }
    __syncthreads();

    for (int rr = 0; rr < 8; rr++) {
        const int r = w * 8 + rr;
        const float wv = wrow[r];
        const int hits = cnt[r];
        if (wv == 0.f || hits == 0) continue;
        const int n = r0 + r;
        const float* yrow = Y + (size_t)n * YROWS + h * Dc;
        float yv[16];
#pragma unroll
        for (int p = 0; p < 16; p++)
            yv[p] = wv * yrow[lane + p * 32];
        for (int j = 0; j < hits; j++) {
            float* arow = attn + (size_t)cm[r * CAND + j] * Dc;
#pragma unroll
            for (int p = 0; p < 16; p++)
                atomicAdd(&arow[lane + p * 32], yv[p]);
        }
    }
}

// --------------------------------------------------------------------------
extern "C" void kernel_launch(void* const* d_in, const int* in_sizes, int n_in,
                              void* d_out, int out_size)
{
    const float* X  = (const float*)d_in[0];
    const float* Kp = (const float*)d_in[1];
    const float* Vp = (const float*)d_in[2];
    const float* W1 = (const float*)d_in[3];
    const float* b1 = (const float*)d_in[4];
    const float* W2 = (const float*)d_in[5];
    const float* b2 = (const float*)d_in[6];

    float *gX, *gAttn, *gY;
    __nv_bfloat16 *gKVh, *gKVl, *gW1h, *gW1l, *gW2h, *gW2l;
    __nv_bfloat16 *gXh, *gXl, *gAth, *gAtl, *gF1h, *gF1l, *gKXh, *gKXl;
    cudaGetSymbolAddress((void**)&gX,   g_X);
    cudaGetSymbolAddress((void**)&gAttn,g_attn);
    cudaGetSymbolAddress((void**)&gY,   g_Y);
    cudaGetSymbolAddress((void**)&gKVh, g_KVh);  cudaGetSymbolAddress((void**)&gKVl, g_KVl);
    cudaGetSymbolAddress((void**)&gW1h, g_W1h);  cudaGetSymbolAddress((void**)&gW1l, g_W1l);
    cudaGetSymbolAddress((void**)&gW2h, g_W2h);  cudaGetSymbolAddress((void**)&gW2l, g_W2l);
    cudaGetSymbolAddress((void**)&gXh,  g_Xh);   cudaGetSymbolAddress((void**)&gXl,  g_Xl);
    cudaGetSymbolAddress((void**)&gAth, g_Ath);  cudaGetSymbolAddress((void**)&gAtl, g_Atl);
    cudaGetSymbolAddress((void**)&gF1h, g_F1h);  cudaGetSymbolAddress((void**)&gF1l, g_F1l);
    cudaGetSymbolAddress((void**)&gKXh, g_KXh);  cudaGetSymbolAddress((void**)&gKXl, g_KXl);

    const int SMBIG = 2 * (2 * 128 * 40 * 2 + 2 * 128 * 40 * 2);  // 81920 (S=2)
    const int SMFF2 = 4 * (2 *  64 * 40 * 2 + 2 *  64 * 40 * 2);  // 81920 (S=4)
    const int SMGR  = 175872;
    cudaFuncSetAttribute(bf16_gemm<128, 128, 2, 4, 2, 2>,
                         cudaFuncAttributeMaxDynamicSharedMemorySize, SMBIG);
    cudaFuncSetAttribute(bf16_gemm<64, 64, 2, 2, 4, 2>,
                         cudaFuncAttributeMaxDynamicSharedMemorySize, SMFF2);
    cudaFuncSetAttribute(gram_argmax_scatter,
                         cudaFuncAttributeMaxDynamicSharedMemorySize, SMGR);

    {
        const int nKV = Lc * KVROWS * Dc / 4;
        const int nW  = Lc * DFFc * Dc / 4;
        pack_kv<<<(nKV + 255) / 256, 256>>>((const float4*)Vp, (const float4*)Kp,
                                            gKVh, gKVl);
        split_kernel<<<(nW + 255) / 256, 256>>>((const float4*)W1, gW1h, gW1l, nW);
        split_kernel<<<(nW + 255) / 256, 256>>>((const float4*)W2, gW2h, gW2l, nW);
        tsplit_generic<<<dim3(2048 / 32, 512 / 32, 1), dim3(32, 8)>>>(
            X, gXh, gXl, gAttn, Dc, Nc);
    }

    for (int l = 0; l < Lc; l++) {
        const float* b1l = b1 + (size_t)l * DFFc;
        const float* b2l = b2 + (size_t)l * Dc;
        const bool last = (l == Lc - 1);

        // 1) [Y | KXt] = Xt @ KV^T  (mode 64, R14 config: 256 thr, 2/SM)
        bf16_gemm<128, 128, 2, 4, 2, 2><<<dim3(KVROWS / 128, Nc / 128, 1), 256, SMBIG>>>(
            gXh, gXl,
            gKVh + (size_t)l * KVROWS * Dc, gKVl + (size_t)l * KVROWS * Dc,
            gY, gKXh, gKXl, Nc, KVROWS, Dc, nullptr, nullptr, 64);

        // 2) fused gram+argmax+scatter
        gram_argmax_scatter<<<dim3(Nc / 64, Hc), 256, SMGR>>>(gKXh, gKXl, gY, gAttn);

        // 3) attn_t planes
        split_kernel<<<(Nc * Dc / 4 + 255) / 256, 256>>>(
            (const float4*)gAttn, gAth, gAtl, Nc * Dc / 4);

        // 4) ff1_t planes = relu(attn_t @ W1^T + b1[col])  (mode 9)
        bf16_gemm<128, 128, 2, 4, 2, 2><<<dim3(DFFc / 128, Nc / 128, 1), 256, SMBIG>>>(
            gAth, gAtl,
            gW1h + (size_t)l * DFFc * Dc, gW1l + (size_t)l * DFFc * Dc,
            nullptr, gF1h, gF1l, Nc, DFFc, Dc, b1l, nullptr, 9);

        // 5) X_t = attn_t + ff1_t @ W2^T + b2[col]
        //    FF2: 64x64 tiles, 128 thr, 256 blocks, 2/SM
        if (last) {
            bf16_gemm<64, 64, 2, 2, 4, 2><<<dim3(Dc / 64, Nc / 64, 1), 128, SMFF2>>>(
                gF1h, gF1l,
                gW2h + (size_t)l * Dc * DFFc, gW2l + (size_t)l * Dc * DFFc,
                gX, nullptr, nullptr, Nc, Dc, DFFc, b2l, gAttn, 6);
        } else {
            bf16_gemm<64, 64, 2, 2, 4, 2><<<dim3(Dc / 64, Nc / 64, 1), 128, SMFF2>>>(
                gF1h, gF1l,
                gW2h + (size_t)l * Dc * DFFc, gW2l + (size_t)l * Dc * DFFc,
                gAttn, gXh, gXl, Nc, Dc, DFFc, b2l, gAttn, 14);
        }
    }

    // final transpose X_t[n][d] -> d_out[d][n]
    tfinal<<<dim3(Dc / 32, Nc / 32, 1), dim3(32, 8)>>>(gX, (float*)d_out);
}

// round 17
// speedup vs baseline: 1.1388x; 1.0461x over previous
#include <cuda_runtime.h>
#include <cuda_bf16.h>
#include <mma.h>
#include <cstdint>

using namespace nvcuda;

#define Lc   8
#define Hc   4
#define Qc   64
#define Dc   512
#define Nc   2048
#define DFFc 2048
#define KVROWS (Hc * Dc + Hc * Qc)   // 2304 output cols: Y then KX
#define YROWS  (Hc * Dc)             // 2048

// ---------------- device scratch (no allocations allowed) ----------------
__device__ float g_X[Nc * Dc];
__device__ float g_attn[Nc * Dc];
__device__ float g_Y[Nc * YROWS];
__device__ __nv_bfloat16 g_KVh[Lc * KVROWS * Dc], g_KVl[Lc * KVROWS * Dc];
__device__ __nv_bfloat16 g_W1h[Lc * DFFc * Dc],   g_W1l[Lc * DFFc * Dc];
__device__ __nv_bfloat16 g_W2h[Lc * Dc * DFFc],   g_W2l[Lc * Dc * DFFc];
__device__ __nv_bfloat16 g_Xh[Nc * Dc],           g_Xl[Nc * Dc];
__device__ __nv_bfloat16 g_Ath[Nc * Dc],          g_Atl[Nc * Dc];
__device__ __nv_bfloat16 g_F1h[Nc * DFFc],        g_F1l[Nc * DFFc];
__device__ __nv_bfloat16 g_KXh[Nc * 256],         g_KXl[Nc * 256];

// ---------------- helpers --------------------------------------------------
__device__ __forceinline__ uint32_t smem_u32(const void* p) {
    uint32_t a;
    asm("{ .reg .u64 t; cvta.to.shared.u64 t, %1; cvt.u32.u64 %0, t; }"
        : "=r"(a) : "l"(p));
    return a;
}
__device__ __forceinline__ void cp16(void* s, const void* g) {
    asm volatile("cp.async.cg.shared.global [%0], [%1], 16;"
                 :: "r"(smem_u32(s)), "l"(g) : "memory");
}
__device__ __forceinline__ void cp_commit() {
    asm volatile("cp.async.commit_group;" ::: "memory");
}
template<int N> __device__ __forceinline__ void cp_wait() {
    asm volatile("cp.async.wait_group %0;" :: "n"(N) : "memory");
}

__device__ __forceinline__ void split_store4(__nv_bfloat16* __restrict__ Hd,
                                             __nv_bfloat16* __restrict__ Ld,
                                             float4 v)
{
    __nv_bfloat162 h0 = __floats2bfloat162_rn(v.x, v.y);
    __nv_bfloat162 h1 = __floats2bfloat162_rn(v.z, v.w);
    float2 f0 = __bfloat1622float2(h0);
    float2 f1 = __bfloat1622float2(h1);
    __nv_bfloat162 l0 = __floats2bfloat162_rn(v.x - f0.x, v.y - f0.y);
    __nv_bfloat162 l1 = __floats2bfloat162_rn(v.z - f1.x, v.w - f1.y);
    *(__nv_bfloat162*)(Hd)     = h0;
    *(__nv_bfloat162*)(Hd + 2) = h1;
    *(__nv_bfloat162*)(Ld)     = l0;
    *(__nv_bfloat162*)(Ld + 2) = l1;
}
__device__ __forceinline__ void split1s(float v, __nv_bfloat16* H, __nv_bfloat16* L) {
    __nv_bfloat16 hv = __float2bfloat16(v);
    *H = hv;
    *L = __float2bfloat16(v - __bfloat162float(hv));
}

__device__ __forceinline__ unsigned enc_f(float f) {
    unsigned u = __float_as_uint(f);
    return (u & 0x80000000u) ? ~u : (u | 0x80000000u);
}
__device__ __forceinline__ float dec_f(unsigned v) {
    return __uint_as_float((v & 0x80000000u) ? (v ^ 0x80000000u) : ~v);
}

// ---------------- plain split ----------------------------------------------
__global__ void __launch_bounds__(256) split_kernel(
    const float4* __restrict__ src,
    __nv_bfloat16* __restrict__ h, __nv_bfloat16* __restrict__ l, int n4)
{
    int i = blockIdx.x * 256 + threadIdx.x;
    if (i < n4) {
        float4 v = src[i];
        split_store4(h + (size_t)i * 4, l + (size_t)i * 4, v);
    }
}

// ---------------- merged weight prep: KV concat + W1 + W2 splits -----------
__global__ void __launch_bounds__(256) prep_weights(
    const float4* __restrict__ V, const float4* __restrict__ K,
    const float4* __restrict__ W1, const float4* __restrict__ W2,
    __nv_bfloat16* __restrict__ KVh, __nv_bfloat16* __restrict__ KVl,
    __nv_bfloat16* __restrict__ W1h, __nv_bfloat16* __restrict__ W1l,
    __nv_bfloat16* __restrict__ W2h, __nv_bfloat16* __restrict__ W2l)
{
    constexpr int NKV = Lc * KVROWS * (Dc / 4);      // 2,359,296
    constexpr int NW  = Lc * DFFc * (Dc / 4);        // 2,097,152
    constexpr int PER_L = KVROWS * (Dc / 4);
    int i = blockIdx.x * 256 + threadIdx.x;
    if (i < NKV) {
        const int lay = i / PER_L;
        const int rem = i % PER_L;
        const int row = rem >> 7;
        const int c4  = rem & 127;
        float4 v = (row < YROWS)
            ? V[((size_t)lay * YROWS + row) * 128 + c4]
            : K[((size_t)lay * (Hc * Qc) + row - YROWS) * 128 + c4];
        split_store4(KVh + (size_t)i * 4, KVl + (size_t)i * 4, v);
    } else if (i < NKV + NW) {
        const int j = i - NKV;
        split_store4(W1h + (size_t)j * 4, W1l + (size_t)j * 4, W1[j]);
    } else if (i < NKV + 2 * NW) {
        const int j = i - NKV - NW;
        split_store4(W2h + (size_t)j * 4, W2l + (size_t)j * 4, W2[j]);
    }
}

// ---------------- X transpose + split (init only) ---------------------------
__global__ void __launch_bounds__(256) tsplit_generic(
    const float* __restrict__ src,
    __nv_bfloat16* __restrict__ dH, __nv_bfloat16* __restrict__ dL,
    float* __restrict__ copyT, int R, int C)
{
    __shared__ float t[32][33];
    const size_t bo = (size_t)blockIdx.z * R * C;
    const int tx = threadIdx.x, ty = threadIdx.y;
    const int x  = blockIdx.x * 32 + tx;
    const int y0 = blockIdx.y * 32;
#pragma unroll
    for (int j = 0; j < 4; j++)
        t[ty + j * 8][tx] = src[bo + (size_t)(y0 + ty + j * 8) * C + x];
    __syncthreads();
#pragma unroll
    for (int j = 0; j < 4; j++) {
        const int k = blockIdx.x * 32 + ty + j * 8;
        const int r = y0 + tx;
        const float v = t[tx][ty + j * 8];
        const size_t di = bo + (size_t)k * R + r;
        split1s(v, dH + di, dL + di);
        if (copyT) copyT[di] = v;
    }
}

// ---------------- final transpose: Xt[n][d] -> out[d][n] --------------------
__global__ void __launch_bounds__(256) tfinal(
    const float* __restrict__ Xt, float* __restrict__ out)
{
    __shared__ float t[32][33];
    const int tx = threadIdx.x, ty = threadIdx.y;
    const int x  = blockIdx.x * 32 + tx;
    const int y0 = blockIdx.y * 32;
#pragma unroll
    for (int j = 0; j < 4; j++)
        t[ty + j * 8][tx] = Xt[(size_t)(y0 + ty + j * 8) * Dc + x];
    __syncthreads();
#pragma unroll
    for (int j = 0; j < 4; j++) {
        const int d = blockIdx.x * 32 + ty + j * 8;
        const int n = y0 + tx;
        out[(size_t)d * Nc + n] = t[tx][ty + j * 8];
    }
}

// ============ bf16-plane 3x GEMM: C[m][n] = sum_k A[m][k]*B[n][k] ==========
template<int BM, int BN, int WM, int WN, int S, int MINB>
__global__ void __launch_bounds__(WM * WN * 32, MINB) bf16_gemm(
    const __nv_bfloat16* __restrict__ Ah, const __nv_bfloat16* __restrict__ Al,
    const __nv_bfloat16* __restrict__ Bh, const __nv_bfloat16* __restrict__ Bl,
    float* __restrict__ C,
    __nv_bfloat16* __restrict__ Ch, __nv_bfloat16* __restrict__ Cl,
    int M, int N, int K,
    const float* __restrict__ bias, const float* __restrict__ R, int mode)
{
    constexpr int TH = WM * WN * 32;
    constexpr int BK = 32;
    constexpr int AP = 40;
    constexpr int BKP = 40;
    constexpr int ABYT = BM * AP * 2;
    constexpr int BBYT = BN * BKP * 2;
    constexpr int STG = 2 * ABYT + 2 * BBYT;
    constexpr int MF = BM / (WM * 16);
    constexpr int NF = BN / (WN * 16);
    constexpr int AIT = BM * (BK / 8) / TH;
    constexpr int BIT = BN * (BK / 8) / TH;

    extern __shared__ char sm[];
    const int tid = threadIdx.x, w = tid >> 5;
    const int bm = blockIdx.y * BM;
    const int bn = blockIdx.x * BN;
    const int wm0 = (w % WM) * (MF * 16);
    const int wn0 = (w / WM) * (NF * 16);
    const int KT = K / BK;

    auto issue = [&](int tile) {
        const int k0 = tile * BK;
        char* st = sm + (tile % S) * STG;
        __nv_bfloat16* sAh = (__nv_bfloat16*)st;
        __nv_bfloat16* sAl = (__nv_bfloat16*)(st + ABYT);
        __nv_bfloat16* sBh = (__nv_bfloat16*)(st + 2 * ABYT);
        __nv_bfloat16* sBl = (__nv_bfloat16*)(st + 2 * ABYT + BBYT);
#pragma unroll
        for (int p = 0; p < AIT; p++) {
            const int c = tid + p * TH;
            const int r = c >> 2, c8 = (c & 3) * 8;
            cp16(sAh + r * AP + c8, Ah + (size_t)(bm + r) * K + k0 + c8);
            cp16(sAl + r * AP + c8, Al + (size_t)(bm + r) * K + k0 + c8);
        }
#pragma unroll
        for (int p = 0; p < BIT; p++) {
            const int c = tid + p * TH;
            const int r = c >> 2, c8 = (c & 3) * 8;
            cp16(sBh + r * BKP + c8, Bh + (size_t)(bn + r) * K + k0 + c8);
            cp16(sBl + r * BKP + c8, Bl + (size_t)(bn + r) * K + k0 + c8);
        }
    };

    wmma::fragment<wmma::accumulator, 16, 16, 16, float> acc[MF][NF];
#pragma unroll
    for (int i = 0; i < MF; i++)
#pragma unroll
        for (int j = 0; j < NF; j++) wmma::fill_fragment(acc[i][j], 0.f);

#pragma unroll
    for (int t = 0; t < S - 1; t++) {
        if (t < KT) issue(t);
        cp_commit();
    }

#pragma unroll 1
    for (int kt = 0; kt < KT; kt++) {
        cp_wait<S - 2>();
        __syncthreads();
        if (kt + S - 1 < KT) issue(kt + S - 1);
        cp_commit();

        char* st = sm + (kt % S) * STG;
        const __nv_bfloat16* sAh = (const __nv_bfloat16*)st;
        const __nv_bfloat16* sAl = (const __nv_bfloat16*)(st + ABYT);
        const __nv_bfloat16* sBh = (const __nv_bfloat16*)(st + 2 * ABYT);
        const __nv_bfloat16* sBl = (const __nv_bfloat16*)(st + 2 * ABYT + BBYT);

#pragma unroll
        for (int kks = 0; kks < 2; kks++) {
            const int kk = kks * 16;
            wmma::fragment<wmma::matrix_a, 16, 16, 16, __nv_bfloat16, wmma::row_major> fAh[MF];
            wmma::fragment<wmma::matrix_b, 16, 16, 16, __nv_bfloat16, wmma::col_major> fBh[NF];
#pragma unroll
            for (int i = 0; i < MF; i++)
                wmma::load_matrix_sync(fAh[i], sAh + (wm0 + i * 16) * AP + kk, AP);
#pragma unroll
            for (int j = 0; j < NF; j++)
                wmma::load_matrix_sync(fBh[j], sBh + (wn0 + j * 16) * BKP + kk, BKP);
#pragma unroll
            for (int i = 0; i < MF; i++)
#pragma unroll
                for (int j = 0; j < NF; j++)
                    wmma::mma_sync(acc[i][j], fAh[i], fBh[j], acc[i][j]);
            {
                wmma::fragment<wmma::matrix_b, 16, 16, 16, __nv_bfloat16, wmma::col_major> fBl[NF];
#pragma unroll
                for (int j = 0; j < NF; j++)
                    wmma::load_matrix_sync(fBl[j], sBl + (wn0 + j * 16) * BKP + kk, BKP);
#pragma unroll
                for (int i = 0; i < MF; i++)
#pragma unroll
                    for (int j = 0; j < NF; j++)
                        wmma::mma_sync(acc[i][j], fAh[i], fBl[j], acc[i][j]);
            }
            {
                wmma::fragment<wmma::matrix_a, 16, 16, 16, __nv_bfloat16, wmma::row_major> fAl[MF];
#pragma unroll
                for (int i = 0; i < MF; i++)
                    wmma::load_matrix_sync(fAl[i], sAl + (wm0 + i * 16) * AP + kk, AP);
#pragma unroll
                for (int i = 0; i < MF; i++)
#pragma unroll
                    for (int j = 0; j < NF; j++)
                        wmma::mma_sync(acc[i][j], fAl[i], fBh[j], acc[i][j]);
            }
        }
    }

    if (mode == 64) {
        if (bn < YROWS) {
#pragma unroll
            for (int i = 0; i < MF; i++)
#pragma unroll
                for (int j = 0; j < NF; j++)
                    wmma::store_matrix_sync(
                        &C[(size_t)(bm + wm0 + i * 16) * YROWS + bn + wn0 + j * 16],
                        acc[i][j], YROWS, wmma::mem_row_major);
        } else {
            __syncthreads();
            float* cs = (float*)sm;
#pragma unroll
            for (int i = 0; i < MF; i++)
#pragma unroll
                for (int j = 0; j < NF; j++)
                    wmma::store_matrix_sync(
                        cs + (size_t)(wm0 + i * 16) * BN + wn0 + j * 16,
                        acc[i][j], BN, wmma::mem_row_major);
            __syncthreads();
            constexpr int CIT2 = BM * BN / 4 / TH;
#pragma unroll
            for (int p = 0; p < CIT2; p++) {
                const int id = tid + p * TH;
                const int row = id / (BN / 4), c4 = id % (BN / 4);
                float4 v = ((const float4*)cs)[id];
                const int gr = bm + row;
                const int gcl = bn - YROWS + c4 * 4;
                split_store4(Ch + (size_t)gr * 256 + gcl,
                             Cl + (size_t)gr * 256 + gcl, v);
            }
        }
        return;
    }

    __syncthreads();
    float* cs = (float*)sm;
#pragma unroll
    for (int i = 0; i < MF; i++)
#pragma unroll
        for (int j = 0; j < NF; j++)
            wmma::store_matrix_sync(cs + (size_t)(wm0 + i * 16) * BN + wn0 + j * 16,
                                    acc[i][j], BN, wmma::mem_row_major);
    __syncthreads();

    constexpr int CIT = BM * BN / 4 / TH;
#pragma unroll
    for (int p = 0; p < CIT; p++) {
        const int id = tid + p * TH;
        const int row = id / (BN / 4), c4 = id % (BN / 4);
        float4 v = ((const float4*)cs)[id];
        const int gr = bm + row;
        const int gc = bn + c4 * 4;
        if (mode & 3) {
            float4 bv = *(const float4*)&bias[gc];
            v.x += bv.x; v.y += bv.y; v.z += bv.z; v.w += bv.w;
        }
        if (mode & 1) {
            v.x = fmaxf(v.x, 0.f); v.y = fmaxf(v.y, 0.f);
            v.z = fmaxf(v.z, 0.f); v.w = fmaxf(v.w, 0.f);
        }
        if (mode & 2) {
            float4 r4 = *(const float4*)&R[(size_t)gr * N + gc];
            v.x += r4.x; v.y += r4.y; v.z += r4.z; v.w += r4.w;
        }
        if (mode & 4) *(float4*)&C[(size_t)gr * N + gc] = v;
        if (mode & 8) split_store4(Ch + (size_t)gr * N + gc,
                                   Cl + (size_t)gr * N + gc, v);
    }
}

// ====== fused gram + argmax + scatter (32-row stripes, 2 blocks/SM) ========
// 256 blocks (64 stripes x 4 heads), 256 threads, warp tile 16x32.
#define CAND 56
__global__ void __launch_bounds__(256, 2) gram_argmax_scatter(
    const __nv_bfloat16* __restrict__ KXh, const __nv_bfloat16* __restrict__ KXl,
    const float* __restrict__ Y, float* __restrict__ attn)
{
    constexpr int AP = 72, BP = 72, CP = 132;
    extern __shared__ char sm[];
    // layout (bytes):
    // aH 0..4608, aL 4608..9216
    // B stages: 9216 + s*36864 (bH 18432 | bL 18432), s=0,1 -> ends 82944
    // Cs 82944..99840 (32*132*4 = 16896)
    // rm 99840(+128), cnt 99968(+128), wrow 100096(+128)
    // cm 100224..107392 (32*56*4), csv 107392..114560
    __nv_bfloat16* aH = (__nv_bfloat16*)sm;
    __nv_bfloat16* aL = (__nv_bfloat16*)(sm + 4608);
    float*    Cs   = (float*)(sm + 82944);
    unsigned* rm   = (unsigned*)(sm + 99840);
    int*      cnt  = (int*)(sm + 99968);
    float*    wrow = (float*)(sm + 100096);
    int*      cm   = (int*)(sm + 100224);
    float*    csv  = (float*)(sm + 107392);

    const int h  = blockIdx.y;
    const int r0 = blockIdx.x * 32;
    const int co = h * 64;
    const int tid = threadIdx.x, w = tid >> 5, lane = tid & 31;
    const int wm0 = (w & 1) * 16;          // 2 m-groups of 16
    const int wn0 = (w >> 1) * 32;         // 4 n-groups of 32

    if (tid < 32) { rm[tid] = enc_f(-1e30f); cnt[tid] = 0; }

    auto issueB = [&](int mt, int s) {
        const int m0 = mt * 128;
        __nv_bfloat16* bH = (__nv_bfloat16*)(sm + 9216 + s * 36864);
        __nv_bfloat16* bL = (__nv_bfloat16*)(sm + 9216 + s * 36864 + 18432);
#pragma unroll
        for (int p = 0; p < 4; p++) {
            const int c = tid + p * 256;
            const int r = c >> 3, c8 = (c & 7) * 8;
            cp16(bH + r * BP + c8, KXh + (size_t)(m0 + r) * 256 + co + c8);
            cp16(bL + r * BP + c8, KXl + (size_t)(m0 + r) * 256 + co + c8);
        }
    };

    // A stripe: 32 rows x 64 cols, one cp16 per thread per plane
    {
        const int r = tid >> 3, c8 = (tid & 7) * 8;
        cp16(aH + r * AP + c8, KXh + (size_t)(r0 + r) * 256 + co + c8);
        cp16(aL + r * AP + c8, KXl + (size_t)(r0 + r) * 256 + co + c8);
    }
    issueB(0, 0);
    cp_commit();

    for (int mt = 0; mt < Nc / 128; mt++) {
        if (mt + 1 < Nc / 128) issueB(mt + 1, (mt + 1) & 1);
        cp_commit();
        cp_wait<1>();
        __syncthreads();

        const __nv_bfloat16* bH = (const __nv_bfloat16*)(sm + 9216 + (mt & 1) * 36864);
        const __nv_bfloat16* bL = bH + 18432 / 2;

        wmma::fragment<wmma::accumulator, 16, 16, 16, float> acc[2];
#pragma unroll
        for (int j = 0; j < 2; j++) wmma::fill_fragment(acc[j], 0.f);

#pragma unroll
        for (int kks = 0; kks < 4; kks++) {
            const int kk = kks * 16;
            wmma::fragment<wmma::matrix_a, 16, 16, 16, __nv_bfloat16, wmma::row_major> fAh;
            wmma::fragment<wmma::matrix_b, 16, 16, 16, __nv_bfloat16, wmma::col_major> fBh[2];
            wmma::load_matrix_sync(fAh, aH + wm0 * AP + kk, AP);
#pragma unroll
            for (int j = 0; j < 2; j++)
                wmma::load_matrix_sync(fBh[j], bH + (wn0 + j * 16) * BP + kk, BP);
#pragma unroll
            for (int j = 0; j < 2; j++)
                wmma::mma_sync(acc[j], fAh, fBh[j], acc[j]);
            {
                wmma::fragment<wmma::matrix_b, 16, 16, 16, __nv_bfloat16, wmma::col_major> fBl[2];
#pragma unroll
                for (int j = 0; j < 2; j++)
                    wmma::load_matrix_sync(fBl[j], bL + (wn0 + j * 16) * BP + kk, BP);
#pragma unroll
                for (int j = 0; j < 2; j++)
                    wmma::mma_sync(acc[j], fAh, fBl[j], acc[j]);
            }
            {
                wmma::fragment<wmma::matrix_a, 16, 16, 16, __nv_bfloat16, wmma::row_major> fAl;
                wmma::load_matrix_sync(fAl, aL + wm0 * AP + kk, AP);
#pragma unroll
                for (int j = 0; j < 2; j++)
                    wmma::mma_sync(acc[j], fAl, fBh[j], acc[j]);
            }
        }
#pragma unroll
        for (int j = 0; j < 2; j++)
            wmma::store_matrix_sync(Cs + wm0 * CP + wn0 + j * 16,
                                    acc[j], CP, wmma::mem_row_major);
        __syncthreads();

        // per-row tile max: r = tid>>3 (0..31), 16 cols per thread
        const int r = tid >> 3;
        const int c0 = (tid & 7) * 16;
        float tm = -1e30f;
#pragma unroll
        for (int c = 0; c < 16; c++) tm = fmaxf(tm, Cs[r * CP + c0 + c]);
        tm = fmaxf(tm, __shfl_xor_sync(0xffffffffu, tm, 1, 8));
        tm = fmaxf(tm, __shfl_xor_sync(0xffffffffu, tm, 2, 8));
        tm = fmaxf(tm, __shfl_xor_sync(0xffffffffu, tm, 4, 8));
        if ((tid & 7) == 0) atomicMax(&rm[r], enc_f(tm));
        __syncthreads();

        const float thr = dec_f(rm[r]) - 0.5f;
        const int m0 = mt * 128;
#pragma unroll
        for (int c = 0; c < 16; c++) {
            const float v = Cs[r * CP + c0 + c];
            if (v >= thr) {
                int pos = atomicAdd(&cnt[r], 1);
                if (pos < CAND) {
                    cm[r * CAND + pos]  = m0 + c0 + c;
                    csv[r * CAND + pos] = v;
                }
            }
        }
        __syncthreads();
    }

    if (tid < 32) {
        const float fmax = dec_f(rm[tid]);
        const float thrF = fmax - 0.5f;
        const int nc = cnt[tid] < CAND ? cnt[tid] : CAND;
        int hits = 0;
        for (int j = 0; j < nc; j++) {
            if (csv[tid * CAND + j] >= thrF) {
                cm[tid * CAND + hits] = cm[tid * CAND + j];
                hits++;
            }
        }
        cnt[tid] = hits;
        wrow[tid] = (fabsf(fmax) > 0.5f && hits > 0) ? 1.f / (float)hits : 0.f;
    }
    __syncthreads();

    // scatter: 8 warps x 4 rows each
    for (int rr = 0; rr < 4; rr++) {
        const int r = w * 4 + rr;
        const float wv = wrow[r];
        const int hits = cnt[r];
        if (wv == 0.f || hits == 0) continue;
        const int n = r0 + r;
        const float* yrow = Y + (size_t)n * YROWS + h * Dc;
        float yv[16];
#pragma unroll
        for (int p = 0; p < 16; p++)
            yv[p] = wv * yrow[lane + p * 32];
        for (int j = 0; j < hits; j++) {
            float* arow = attn + (size_t)cm[r * CAND + j] * Dc;
#pragma unroll
            for (int p = 0; p < 16; p++)
                atomicAdd(&arow[lane + p * 32], yv[p]);
        }
    }
}

// --------------------------------------------------------------------------
extern "C" void kernel_launch(void* const* d_in, const int* in_sizes, int n_in,
                              void* d_out, int out_size)
{
    const float* X  = (const float*)d_in[0];
    const float* Kp = (const float*)d_in[1];
    const float* Vp = (const float*)d_in[2];
    const float* W1 = (const float*)d_in[3];
    const float* b1 = (const float*)d_in[4];
    const float* W2 = (const float*)d_in[5];
    const float* b2 = (const float*)d_in[6];

    float *gX, *gAttn, *gY;
    __nv_bfloat16 *gKVh, *gKVl, *gW1h, *gW1l, *gW2h, *gW2l;
    __nv_bfloat16 *gXh, *gXl, *gAth, *gAtl, *gF1h, *gF1l, *gKXh, *gKXl;
    cudaGetSymbolAddress((void**)&gX,   g_X);
    cudaGetSymbolAddress((void**)&gAttn,g_attn);
    cudaGetSymbolAddress((void**)&gY,   g_Y);
    cudaGetSymbolAddress((void**)&gKVh, g_KVh);  cudaGetSymbolAddress((void**)&gKVl, g_KVl);
    cudaGetSymbolAddress((void**)&gW1h, g_W1h);  cudaGetSymbolAddress((void**)&gW1l, g_W1l);
    cudaGetSymbolAddress((void**)&gW2h, g_W2h);  cudaGetSymbolAddress((void**)&gW2l, g_W2l);
    cudaGetSymbolAddress((void**)&gXh,  g_Xh);   cudaGetSymbolAddress((void**)&gXl,  g_Xl);
    cudaGetSymbolAddress((void**)&gAth, g_Ath);  cudaGetSymbolAddress((void**)&gAtl, g_Atl);
    cudaGetSymbolAddress((void**)&gF1h, g_F1h);  cudaGetSymbolAddress((void**)&gF1l, g_F1l);
    cudaGetSymbolAddress((void**)&gKXh, g_KXh);  cudaGetSymbolAddress((void**)&gKXl, g_KXl);

    const int SMBIG = 2 * (2 * 128 * 40 * 2 + 2 * 128 * 40 * 2);  // 81920 (S=2)
    const int SMFF2 = 4 * (2 *  64 * 40 * 2 + 2 *  64 * 40 * 2);  // 81920 (S=4)
    const int SMGR  = 114560;
    cudaFuncSetAttribute(bf16_gemm<128, 128, 2, 4, 2, 2>,
                         cudaFuncAttributeMaxDynamicSharedMemorySize, SMBIG);
    cudaFuncSetAttribute(bf16_gemm<64, 64, 2, 2, 4, 2>,
                         cudaFuncAttributeMaxDynamicSharedMemorySize, SMFF2);
    cudaFuncSetAttribute(gram_argmax_scatter,
                         cudaFuncAttributeMaxDynamicSharedMemorySize, SMGR);

    {
        const int nTot = Lc * KVROWS * (Dc / 4) + 2 * Lc * DFFc * (Dc / 4);
        prep_weights<<<(nTot + 255) / 256, 256>>>(
            (const float4*)Vp, (const float4*)Kp,
            (const float4*)W1, (const float4*)W2,
            gKVh, gKVl, gW1h, gW1l, gW2h, gW2l);
        tsplit_generic<<<dim3(2048 / 32, 512 / 32, 1), dim3(32, 8)>>>(
            X, gXh, gXl, gAttn, Dc, Nc);
    }

    for (int l = 0; l < Lc; l++) {
        const float* b1l = b1 + (size_t)l * DFFc;
        const float* b2l = b2 + (size_t)l * Dc;
        const bool last = (l == Lc - 1);

        // 1) [Y | KXt] = Xt @ KV^T
        bf16_gemm<128, 128, 2, 4, 2, 2><<<dim3(KVROWS / 128, Nc / 128, 1), 256, SMBIG>>>(
            gXh, gXl,
            gKVh + (size_t)l * KVROWS * Dc, gKVl + (size_t)l * KVROWS * Dc,
            gY, gKXh, gKXl, Nc, KVROWS, Dc, nullptr, nullptr, 64);

        // 2) fused gram+argmax+scatter (256 blocks, 2/SM)
        gram_argmax_scatter<<<dim3(Nc / 32, Hc), 256, SMGR>>>(gKXh, gKXl, gY, gAttn);

        // 3) attn_t planes
        split_kernel<<<(Nc * Dc / 4 + 255) / 256, 256>>>(
            (const float4*)gAttn, gAth, gAtl, Nc * Dc / 4);

        // 4) ff1_t planes = relu(attn_t @ W1^T + b1[col])
        bf16_gemm<128, 128, 2, 4, 2, 2><<<dim3(DFFc / 128, Nc / 128, 1), 256, SMBIG>>>(
            gAth, gAtl,
            gW1h + (size_t)l * DFFc * Dc, gW1l + (size_t)l * DFFc * Dc,
            nullptr, gF1h, gF1l, Nc, DFFc, Dc, b1l, nullptr, 9);

        // 5) X_t = attn_t + ff1_t @ W2^T + b2[col]
        if (last) {
            bf16_gemm<64, 64, 2, 2, 4, 2><<<dim3(Dc / 64, Nc / 64, 1), 128, SMFF2>>>(
                gF1h, gF1l,
                gW2h + (size_t)l * Dc * DFFc, gW2l + (size_t)l * Dc * DFFc,
                gX, nullptr, nullptr, Nc, Dc, DFFc, b2l, gAttn, 6);
        } else {
            bf16_gemm<64, 64, 2, 2, 4, 2><<<dim3(Dc / 64, Nc / 64, 1), 128, SMFF2>>>(
                gF1h, gF1l,
                gW2h + (size_t)l * Dc * DFFc, gW2l + (size_t)l * Dc * DFFc,
                gAttn, gXh, gXl, Nc, Dc, DFFc, b2l, gAttn, 14);
        }
    }

    // final transpose X_t[n][d] -> d_out[d][n]
    tfinal<<<dim3(Dc / 32, Nc / 32, 1), dim3(32, 8)>>>(gX, (float*)d_out);
}